// round 8
// baseline (speedup 1.0000x reference)
#include <cuda_runtime.h>
#include <cstdint>

// ---------------- problem dims (fixed by dataset) ----------------
#define S_LEN  512
#define BATCH  512
#define VOCAB  50000
#define EDIM   50
#define HDIM   128
#define G3     384          // 3*H
#define NROWS  1024         // 2 sequences * BATCH

// GRU kernel geometry: 147 CTAs x 7 rows covers 1029 >= 1024 rows
#define RPC    7            // rows per CTA
#define NCTA   147

typedef unsigned long long ull;

// ---------------- device scratch (no cudaMalloc allowed) ----------------
__device__ float g_emb_proj[(size_t)VOCAB * G3];   // 76.8 MB: W_ih @ emb[v] + b_ih
__device__ float g_hfinal[NROWS * HDIM];           // rows 0..511 = seq1, 512..1023 = seq2

// ---------------- helpers ----------------
__device__ __forceinline__ void ffma2(ull &acc, ull a, ull b) {
    asm("fma.rn.f32x2 %0, %1, %2, %0;" : "+l"(acc) : "l"(a), "l"(b));
}
__device__ __forceinline__ float lane_lo(ull v) { return __uint_as_float((unsigned)v); }
__device__ __forceinline__ float lane_hi(ull v) { return __uint_as_float((unsigned)(v >> 32)); }
__device__ __forceinline__ float sigf(float x) {
    return __fdividef(1.f, 1.f + __expf(-x));
}
__device__ __forceinline__ float tanh_f(float x) {     // 2*sig(2x)-1, ~1e-6 err
    return __fdividef(2.f, 1.f + __expf(-2.f * x)) - 1.f;
}

// =================================================================
// Kernel A: emb_proj[v][g] = b_ih[g] + sum_e emb[v][e] * W_ih[g][e]
// (unchanged, verified)
// =================================================================
#define A_VB 64

__global__ __launch_bounds__(384) void emb_proj_kernel(
        const float* __restrict__ emb,
        const float* __restrict__ W_ih,
        const float* __restrict__ b_ih) {
    __shared__ __align__(16) float emb_s[A_VB * 52];   // padded pitch 52

    const int g  = threadIdx.x;                        // 0..383
    const int v0 = blockIdx.x * A_VB;

    for (int idx = g; idx < A_VB * EDIM; idx += 384) {
        int v = idx / EDIM, e = idx % EDIM;
        float val = 0.f;
        if (v0 + v < VOCAB) val = emb[(size_t)(v0 + v) * EDIM + e];
        emb_s[v * 52 + e] = val;
    }

    ull w2[25];
    const ull* wrow = reinterpret_cast<const ull*>(W_ih + g * EDIM);
#pragma unroll
    for (int ep = 0; ep < 25; ep++) w2[ep] = __ldg(&wrow[ep]);
    const float bias = __ldg(&b_ih[g]);

    __syncthreads();

    for (int vb = 0; vb < A_VB; vb += 4) {
        ull a0 = 0, a1 = 0, a2 = 0, a3 = 0;
        const ull* e0 = reinterpret_cast<const ull*>(&emb_s[(vb + 0) * 52]);
        const ull* e1 = reinterpret_cast<const ull*>(&emb_s[(vb + 1) * 52]);
        const ull* e2 = reinterpret_cast<const ull*>(&emb_s[(vb + 2) * 52]);
        const ull* e3 = reinterpret_cast<const ull*>(&emb_s[(vb + 3) * 52]);
#pragma unroll
        for (int ep = 0; ep < 25; ep++) {
            ull w = w2[ep];
            ffma2(a0, w, e0[ep]);
            ffma2(a1, w, e1[ep]);
            ffma2(a2, w, e2[ep]);
            ffma2(a3, w, e3[ep]);
        }
        float s0 = lane_lo(a0) + lane_hi(a0) + bias;
        float s1 = lane_lo(a1) + lane_hi(a1) + bias;
        float s2 = lane_lo(a2) + lane_hi(a2) + bias;
        float s3 = lane_lo(a3) + lane_hi(a3) + bias;
        if (v0 + vb + 0 < VOCAB) g_emb_proj[(size_t)(v0 + vb + 0) * G3 + g] = s0;
        if (v0 + vb + 1 < VOCAB) g_emb_proj[(size_t)(v0 + vb + 1) * G3 + g] = s1;
        if (v0 + vb + 2 < VOCAB) g_emb_proj[(size_t)(v0 + vb + 2) * G3 + g] = s2;
        if (v0 + vb + 3 < VOCAB) g_emb_proj[(size_t)(v0 + vb + 3) * G3 + g] = s3;
    }
}

// ---------------- tiny no-op (shifts ncu capture onto the GRU) ----------------
__global__ void noop_kernel() {}

// =================================================================
// Kernel B: persistent GRU. 147 CTAs x 7 rows, 384 threads (12 warps).
// Thread = gate row g. W_hh row in 64 ull registers. h broadcast LDS.
// gx gathered global->SMEM via cp.async (zero register footprint).
// Register budget: W 128 + acc 14 + hv 4 + misc ~15  <= 168 (no spills).
// =================================================================
__global__ __launch_bounds__(384, 1) void gru_kernel(
        const int*   __restrict__ x1,
        const int*   __restrict__ x2,
        const float* __restrict__ W_hh,
        const float* __restrict__ b_hh) {
    __shared__ __align__(16) float h_s[RPC * HDIM];    // 896 floats
    __shared__ __align__(16) float A_s[RPC * G3];      // 2688 floats (ghh + b_hh)
    __shared__ __align__(16) float GXA[RPC * G3];      // 2688 floats (gx tile)
    __shared__ int tok[RPC];

    const int g    = threadIdx.x;          // 0..383 (gate row)
    const int row0 = blockIdx.x * RPC;

    // ---- W_hh[g][0..127] into registers (one-time) ----
    ull w2[64];
    {
        const ulonglong2* wrow =
            reinterpret_cast<const ulonglong2*>(W_hh + g * HDIM);
#pragma unroll
        for (int c = 0; c < 32; c++) {
            ulonglong2 v = __ldg(&wrow[c]);
            w2[2 * c]     = v.x;
            w2[2 * c + 1] = v.y;
        }
    }
    const float bhh = __ldg(&b_hh[g]);

    // gx destination SMEM addresses (u32 shared space)
    const unsigned gxa_base =
        (unsigned)__cvta_generic_to_shared(&GXA[0]) + (unsigned)(g * 4);

    // h = 0
    for (int idx = g; idx < RPC * HDIM; idx += 384) h_s[idx] = 0.f;
    // tokens for step 0
    if (g < RPC) {
        int row = row0 + g; if (row > NROWS - 1) row = NROWS - 1;
        tok[g] = (row < BATCH) ? x1[row] : x2[row - BATCH];
    }
    __syncthreads();

    for (int t = 0; t < S_LEN; t++) {
        // ---- issue gx gathers: global -> SMEM, no registers held ----
#pragma unroll
        for (int r = 0; r < RPC; r++) {
            const float* src = &g_emb_proj[(size_t)tok[r] * G3 + g];
            unsigned dst = gxa_base + (unsigned)(r * G3 * 4);
            asm volatile("cp.async.ca.shared.global [%0], [%1], 4;"
                         :: "r"(dst), "l"(src));
        }
        asm volatile("cp.async.commit_group;");

        // ---- ghh[g][r] = sum_k W[g][k] * h[r][k]  (W regs, h broadcast) ----
        ull acc[RPC];
#pragma unroll
        for (int r = 0; r < RPC; r++) acc[r] = 0ull;

#pragma unroll
        for (int c = 0; c < 32; c++) {              // 4 floats per chunk
            ull wa = w2[2 * c], wb = w2[2 * c + 1];
#pragma unroll
            for (int r = 0; r < RPC; r++) {
                ulonglong2 hv = reinterpret_cast<const ulonglong2*>(
                                    h_s + r * HDIM)[c];
                ffma2(acc[r], wa, hv.x);
                ffma2(acc[r], wb, hv.y);
            }
        }

        // ---- publish pre-activations (ghh + b_hh only; gx folded later) ----
#pragma unroll
        for (int r = 0; r < RPC; r++)
            A_s[r * G3 + g] = lane_lo(acc[r]) + lane_hi(acc[r]) + bhh;

        asm volatile("cp.async.wait_group 0;");
        __syncthreads();

        // ---- gate math + h update (896 items / 384 threads) ----
        for (int item = g; item < RPC * HDIM; item += 384) {
            int r = item >> 7, j = item & 127;
            float rr = sigf(A_s[r * G3 + j] + GXA[r * G3 + j]);
            float zz = sigf(A_s[r * G3 + HDIM + j] + GXA[r * G3 + HDIM + j]);
            float nn = tanh_f(GXA[r * G3 + 2 * HDIM + j]
                              + rr * A_s[r * G3 + 2 * HDIM + j]);
            float hv = h_s[item];
            h_s[item] = nn + zz * (hv - nn);
        }
        // tokens for next step (current tok consumed at step top)
        if (t + 1 < S_LEN && g < RPC) {
            int row = row0 + g; if (row > NROWS - 1) row = NROWS - 1;
            tok[g] = (row < BATCH) ? x1[(t + 1) * BATCH + row]
                                   : x2[(t + 1) * BATCH + row - BATCH];
        }
        __syncthreads();
    }

    // write final hidden states (skip padded rows)
    for (int item = g; item < RPC * HDIM; item += 384) {
        int r = item >> 7, j = item & 127;
        int row = row0 + r;
        if (row < NROWS) g_hfinal[row * HDIM + j] = h_s[item];
    }
}

// =================================================================
// Kernel C: head.  out[b] = sigmoid( W2 . relu(W1 . [h1;h2] + b1) + b2 )
// =================================================================
__global__ __launch_bounds__(128) void head_kernel(
        const float* __restrict__ W1, const float* __restrict__ b1,
        const float* __restrict__ W2, const float* __restrict__ b2,
        float* __restrict__ out) {
    __shared__ float fc[2 * HDIM];
    __shared__ float red[HDIM];
    const int b = blockIdx.x, j = threadIdx.x;

    fc[j]        = g_hfinal[b * HDIM + j];
    fc[HDIM + j] = g_hfinal[(BATCH + b) * HDIM + j];
    __syncthreads();

    float acc = __ldg(&b1[j]);
    const float* wr = W1 + j * 2 * HDIM;
#pragma unroll 8
    for (int k = 0; k < 2 * HDIM; k++) acc = fmaf(fc[k], __ldg(&wr[k]), acc);
    float hid = fmaxf(acc, 0.f);

    red[j] = hid * __ldg(&W2[j]);
    __syncthreads();
    for (int s = 64; s > 0; s >>= 1) {
        if (j < s) red[j] += red[j + s];
        __syncthreads();
    }
    if (j == 0) out[b] = __fdividef(1.f, 1.f + __expf(-(red[0] + __ldg(&b2[0]))));
}

// =================================================================
// launch
// =================================================================
extern "C" void kernel_launch(void* const* d_in, const int* in_sizes, int n_in,
                              void* d_out, int out_size) {
    const int*   x1   = (const int*)  d_in[0];
    const int*   x2   = (const int*)  d_in[1];
    const float* emb  = (const float*)d_in[2];
    const float* W_ih = (const float*)d_in[3];
    const float* W_hh = (const float*)d_in[4];
    const float* b_ih = (const float*)d_in[5];
    const float* b_hh = (const float*)d_in[6];
    const float* W1   = (const float*)d_in[7];
    const float* b1   = (const float*)d_in[8];
    const float* W2   = (const float*)d_in[9];
    const float* b2   = (const float*)d_in[10];
    float* out = (float*)d_out;

    const int a_blocks = (VOCAB + A_VB - 1) / A_VB;   // 782
    emb_proj_kernel<<<a_blocks, 384>>>(emb, W_ih, b_ih);
    // no-op spacers: land ncu's "-s 5 -c 1" capture on the GRU kernel
    noop_kernel<<<1, 32>>>();
    noop_kernel<<<1, 32>>>();
    noop_kernel<<<1, 32>>>();
    noop_kernel<<<1, 32>>>();
    gru_kernel<<<NCTA, 384>>>(x1, x2, W_hh, b_hh);
    head_kernel<<<BATCH, 128>>>(W1, b1, W2, b2, out);
}

// round 9
// speedup vs baseline: 1.1181x; 1.1181x over previous
#include <cuda_runtime.h>
#include <cstdint>

// ---------------- problem dims (fixed by dataset) ----------------
#define S_LEN  512
#define BATCH  512
#define VOCAB  50000
#define EDIM   50
#define HDIM   128
#define G3     384          // 3*H
#define NROWS  1024         // 2 sequences * BATCH

// GRU kernel geometry: 147 CTAs x 7 rows covers 1029 >= 1024 rows
#define RPC    7            // rows per CTA
#define NCTA   147

typedef unsigned long long ull;

// ---------------- device scratch (no cudaMalloc allowed) ----------------
__device__ float g_emb_proj[(size_t)VOCAB * G3];   // 76.8 MB: W_ih @ emb[v] + b_ih
__device__ float g_hfinal[NROWS * HDIM];           // rows 0..511 = seq1, 512..1023 = seq2

// ---------------- helpers ----------------
__device__ __forceinline__ void ffma2(ull &acc, ull a, ull b) {
    asm("fma.rn.f32x2 %0, %1, %2, %0;" : "+l"(acc) : "l"(a), "l"(b));
}
__device__ __forceinline__ float lane_lo(ull v) { return __uint_as_float((unsigned)v); }
__device__ __forceinline__ float lane_hi(ull v) { return __uint_as_float((unsigned)(v >> 32)); }
__device__ __forceinline__ float sigf(float x) {
    return __fdividef(1.f, 1.f + __expf(-x));
}
__device__ __forceinline__ float tanh_f(float x) {     // 2*sig(2x)-1, ~1e-6 err
    return __fdividef(2.f, 1.f + __expf(-2.f * x)) - 1.f;
}

// =================================================================
// Kernel A: emb_proj[v][g] = b_ih[g] + sum_e emb[v][e] * W_ih[g][e]
// (unchanged, verified)
// =================================================================
#define A_VB 64

__global__ __launch_bounds__(384) void emb_proj_kernel(
        const float* __restrict__ emb,
        const float* __restrict__ W_ih,
        const float* __restrict__ b_ih) {
    __shared__ __align__(16) float emb_s[A_VB * 52];   // padded pitch 52

    const int g  = threadIdx.x;                        // 0..383
    const int v0 = blockIdx.x * A_VB;

    for (int idx = g; idx < A_VB * EDIM; idx += 384) {
        int v = idx / EDIM, e = idx % EDIM;
        float val = 0.f;
        if (v0 + v < VOCAB) val = emb[(size_t)(v0 + v) * EDIM + e];
        emb_s[v * 52 + e] = val;
    }

    ull w2[25];
    const ull* wrow = reinterpret_cast<const ull*>(W_ih + g * EDIM);
#pragma unroll
    for (int ep = 0; ep < 25; ep++) w2[ep] = __ldg(&wrow[ep]);
    const float bias = __ldg(&b_ih[g]);

    __syncthreads();

    for (int vb = 0; vb < A_VB; vb += 4) {
        ull a0 = 0, a1 = 0, a2 = 0, a3 = 0;
        const ull* e0 = reinterpret_cast<const ull*>(&emb_s[(vb + 0) * 52]);
        const ull* e1 = reinterpret_cast<const ull*>(&emb_s[(vb + 1) * 52]);
        const ull* e2 = reinterpret_cast<const ull*>(&emb_s[(vb + 2) * 52]);
        const ull* e3 = reinterpret_cast<const ull*>(&emb_s[(vb + 3) * 52]);
#pragma unroll
        for (int ep = 0; ep < 25; ep++) {
            ull w = w2[ep];
            ffma2(a0, w, e0[ep]);
            ffma2(a1, w, e1[ep]);
            ffma2(a2, w, e2[ep]);
            ffma2(a3, w, e3[ep]);
        }
        float s0 = lane_lo(a0) + lane_hi(a0) + bias;
        float s1 = lane_lo(a1) + lane_hi(a1) + bias;
        float s2 = lane_lo(a2) + lane_hi(a2) + bias;
        float s3 = lane_lo(a3) + lane_hi(a3) + bias;
        if (v0 + vb + 0 < VOCAB) g_emb_proj[(size_t)(v0 + vb + 0) * G3 + g] = s0;
        if (v0 + vb + 1 < VOCAB) g_emb_proj[(size_t)(v0 + vb + 1) * G3 + g] = s1;
        if (v0 + vb + 2 < VOCAB) g_emb_proj[(size_t)(v0 + vb + 2) * G3 + g] = s2;
        if (v0 + vb + 3 < VOCAB) g_emb_proj[(size_t)(v0 + vb + 3) * G3 + g] = s3;
    }
}

// ---------------- tiny no-op (shifts ncu capture onto the GRU) ----------------
__global__ void noop_kernel() {}

// =================================================================
// Kernel B: persistent GRU. 147 CTAs x 7 rows, 384 threads (12 warps).
// Thread = gate row g. W_hh row in 64 ull registers. h broadcast LDS.64
// (2-reg buffers -> deeper load-ahead inside the 168-reg cap).
// gxv via __ldg at step top (R6-verified). tok read from SMEM (no tk regs).
// =================================================================
__global__ __launch_bounds__(384, 1) void gru_kernel(
        const int*   __restrict__ x1,
        const int*   __restrict__ x2,
        const float* __restrict__ W_hh,
        const float* __restrict__ b_hh) {
    __shared__ __align__(16) float h_s[RPC * HDIM];    // 896 floats
    __shared__ __align__(16) float A_s[RPC * G3];      // 2688 floats
    __shared__ __align__(16) float GXn[RPC * HDIM];    // 896 floats
    __shared__ int tok[RPC];

    const int g    = threadIdx.x;          // 0..383 (gate row)
    const int row0 = blockIdx.x * RPC;

    // ---- W_hh[g][0..127] into registers (one-time) ----
    ull w2[64];
    {
        const ulonglong2* wrow =
            reinterpret_cast<const ulonglong2*>(W_hh + g * HDIM);
#pragma unroll
        for (int c = 0; c < 32; c++) {
            ulonglong2 v = __ldg(&wrow[c]);
            w2[2 * c]     = v.x;
            w2[2 * c + 1] = v.y;
        }
    }
    const float bhh = __ldg(&b_hh[g]);

    // h = 0
    for (int idx = g; idx < RPC * HDIM; idx += 384) h_s[idx] = 0.f;
    // tokens for step 0
    if (g < RPC) {
        int row = row0 + g; if (row > NROWS - 1) row = NROWS - 1;
        tok[g] = (row < BATCH) ? x1[row] : x2[row - BATCH];
    }
    __syncthreads();

    const ull* hq = reinterpret_cast<const ull*>(h_s);   // 8B view of h_s

    for (int t = 0; t < S_LEN; t++) {
        // ---- gx gather (tok read straight from SMEM; L2 latency hidden) ----
        float gxv[RPC];
#pragma unroll
        for (int r = 0; r < RPC; r++)
            gxv[r] = __ldg(&g_emb_proj[(size_t)tok[r] * G3 + g]);

        // ---- ghh[g][r] = sum_k W[g][k] * h[r][k]  (W regs, h LDS.64) ----
        ull acc[RPC];
#pragma unroll
        for (int r = 0; r < RPC; r++) acc[r] = 0ull;

#pragma unroll
        for (int c = 0; c < 32; c++) {              // 4 floats per chunk
#pragma unroll
            for (int r = 0; r < RPC; r++) {
                ull h0 = hq[r * 64 + 2 * c];        // 2-reg buffers
                ull h1 = hq[r * 64 + 2 * c + 1];
                ffma2(acc[r], w2[2 * c],     h0);
                ffma2(acc[r], w2[2 * c + 1], h1);
            }
        }

        // ---- publish pre-activations ----
#pragma unroll
        for (int r = 0; r < RPC; r++) {
            float a = lane_lo(acc[r]) + lane_hi(acc[r]) + bhh;
            if (g < 2 * HDIM) {
                A_s[r * G3 + g] = a + gxv[r];       // r,z: fold gx in
            } else {
                A_s[r * G3 + g] = a;                // n: ghh only
                GXn[r * HDIM + (g - 2 * HDIM)] = gxv[r];
            }
        }
        __syncthreads();

        // ---- gate math + h update (896 items / 384 threads) ----
        for (int item = g; item < RPC * HDIM; item += 384) {
            int r = item >> 7, j = item & 127;
            float rr = sigf(A_s[r * G3 + j]);
            float zz = sigf(A_s[r * G3 + HDIM + j]);
            float nn = tanh_f(GXn[r * HDIM + j] + rr * A_s[r * G3 + 2 * HDIM + j]);
            float hv = h_s[item];
            h_s[item] = nn + zz * (hv - nn);
        }
        // tokens for next step (current tok consumed at step top)
        if (t + 1 < S_LEN && g < RPC) {
            int row = row0 + g; if (row > NROWS - 1) row = NROWS - 1;
            tok[g] = (row < BATCH) ? x1[(t + 1) * BATCH + row]
                                   : x2[(t + 1) * BATCH + row - BATCH];
        }
        __syncthreads();
    }

    // write final hidden states (skip padded rows)
    for (int item = g; item < RPC * HDIM; item += 384) {
        int r = item >> 7, j = item & 127;
        int row = row0 + r;
        if (row < NROWS) g_hfinal[row * HDIM + j] = h_s[item];
    }
}

// =================================================================
// Kernel C: head.  out[b] = sigmoid( W2 . relu(W1 . [h1;h2] + b1) + b2 )
// =================================================================
__global__ __launch_bounds__(128) void head_kernel(
        const float* __restrict__ W1, const float* __restrict__ b1,
        const float* __restrict__ W2, const float* __restrict__ b2,
        float* __restrict__ out) {
    __shared__ float fc[2 * HDIM];
    __shared__ float red[HDIM];
    const int b = blockIdx.x, j = threadIdx.x;

    fc[j]        = g_hfinal[b * HDIM + j];
    fc[HDIM + j] = g_hfinal[(BATCH + b) * HDIM + j];
    __syncthreads();

    float acc = __ldg(&b1[j]);
    const float* wr = W1 + j * 2 * HDIM;
#pragma unroll 8
    for (int k = 0; k < 2 * HDIM; k++) acc = fmaf(fc[k], __ldg(&wr[k]), acc);
    float hid = fmaxf(acc, 0.f);

    red[j] = hid * __ldg(&W2[j]);
    __syncthreads();
    for (int s = 64; s > 0; s >>= 1) {
        if (j < s) red[j] += red[j + s];
        __syncthreads();
    }
    if (j == 0) out[b] = __fdividef(1.f, 1.f + __expf(-(red[0] + __ldg(&b2[0]))));
}

// =================================================================
// launch
// =================================================================
extern "C" void kernel_launch(void* const* d_in, const int* in_sizes, int n_in,
                              void* d_out, int out_size) {
    const int*   x1   = (const int*)  d_in[0];
    const int*   x2   = (const int*)  d_in[1];
    const float* emb  = (const float*)d_in[2];
    const float* W_ih = (const float*)d_in[3];
    const float* W_hh = (const float*)d_in[4];
    const float* b_ih = (const float*)d_in[5];
    const float* b_hh = (const float*)d_in[6];
    const float* W1   = (const float*)d_in[7];
    const float* b1   = (const float*)d_in[8];
    const float* W2   = (const float*)d_in[9];
    const float* b2   = (const float*)d_in[10];
    float* out = (float*)d_out;

    const int a_blocks = (VOCAB + A_VB - 1) / A_VB;   // 782
    emb_proj_kernel<<<a_blocks, 384>>>(emb, W_ih, b_ih);
    // spacers: put the GRU at the 5th launch (where ncu's capture landed)
    noop_kernel<<<1, 32>>>();
    noop_kernel<<<1, 32>>>();
    noop_kernel<<<1, 32>>>();
    gru_kernel<<<NCTA, 384>>>(x1, x2, W_hh, b_hh);
    head_kernel<<<BATCH, 128>>>(W1, b1, W2, b2, out);
}